// round 9
// baseline (speedup 1.0000x reference)
#include <cuda_runtime.h>
#include <stdint.h>

// Problem constants
#define TT 2048
#define BB 128
#define KK 64
#define NTHREADS 576   // 18 warps: 0-1 = state (A/C), 2-17 = gumbel rows (4 each)

// Opaque 1 in writable device memory: forces mad.lo.u32 (IMAD, fma pipe) to
// survive ptxas -- it cannot prove the multiplier is 1 and fold to IADD3.
__device__ uint32_t g_one = 1u;

// add via IMAD (fma pipe): d = a*one + b. Bit-exact integer add.
__device__ __forceinline__ uint32_t addi(uint32_t a, uint32_t b, uint32_t one) {
    uint32_t r;
    asm("mad.lo.u32 %0, %1, %2, %3;" : "=r"(r) : "r"(a), "r"(one), "r"(b));
    return r;
}

// ---------------------------------------------------------------------------
// Threefry-2x32, 20 rounds, exactly as jax._src.prng.threefry2x32.
// All integer adds forced onto the fma pipe (IMAD) to relieve the saturated
// alu pipe (SHF/LOP3 stay alu). 1:1 substitution, same latency.
// ---------------------------------------------------------------------------
__device__ __forceinline__ uint2 tf2x32(uint32_t k0, uint32_t k1,
                                        uint32_t x0, uint32_t x1,
                                        uint32_t one) {
    uint32_t ks2 = k0 ^ k1 ^ 0x1BD11BDAu;
    x0 = addi(x0, k0, one); x1 = addi(x1, k1, one);
#define TFR(r) { x0 = addi(x0, x1, one);                  \
                 x1 = __funnelshift_l(x1, x1, (r));       \
                 x1 ^= x0; }
    TFR(13) TFR(15) TFR(26) TFR(6)
    x0 = addi(x0, k1, one);  x1 = addi(x1, ks2 + 1u, one);
    TFR(17) TFR(29) TFR(16) TFR(24)
    x0 = addi(x0, ks2, one); x1 = addi(x1, k0 + 2u, one);
    TFR(13) TFR(15) TFR(26) TFR(6)
    x0 = addi(x0, k0, one);  x1 = addi(x1, k1 + 3u, one);
    TFR(17) TFR(29) TFR(16) TFR(24)
    x0 = addi(x0, k1, one);  x1 = addi(x1, ks2 + 4u, one);
    TFR(13) TFR(15) TFR(26) TFR(6)
    x0 = addi(x0, ks2, one); x1 = addi(x1, k0 + 5u, one);
#undef TFR
    return make_uint2(x0, x1);
}

__device__ __forceinline__ float bits_to_u01(uint32_t bits) {
    return __uint_as_float((bits >> 9) | 0x3f800000u) - 1.0f;
}

#define TINYF 1.17549435082228751e-38f

// Fast polynomial -log(u) for u in (0,1). ~16 instr, NO MUFU.
// Relative error ~2e-7 uniformly (log1p form is exact-dominant near u=1).
__device__ __forceinline__ float neglog_poly(uint32_t bits) {
    float u = fmaxf(bits_to_u01(bits), TINYF);
    int   i = __float_as_int(u);
    int   e = (i >> 23) - 127;
    float m = __int_as_float((i & 0x007fffff) | 0x3f800000);  // [1,2)
    if (m > 1.41421356237f) { m *= 0.5f; e += 1; }            // [0.707,1.414]
    float f = m - 1.0f;
    float z = f * f;
    float p =              7.0376836292e-2f;
    p = fmaf(p, f, -1.1514610310e-1f);
    p = fmaf(p, f,  1.1676998740e-1f);
    p = fmaf(p, f, -1.2420140846e-1f);
    p = fmaf(p, f,  1.4249322787e-1f);
    p = fmaf(p, f, -1.6668057665e-1f);
    p = fmaf(p, f,  2.0000714765e-1f);
    p = fmaf(p, f, -2.4999993993e-1f);
    p = fmaf(p, f,  3.3333331174e-1f);
    float y = (f * z) * p;
    float ef = (float)e;
    y = fmaf(ef, -2.12194440e-4f, y);   // ln2 low part
    y = fmaf(z, -0.5f, y);
    float r = f + y + ef * 0.693359375f;  // ln2 high part
    return -r;
}

// XLA/CHLO ErfInv32 polynomial (Giles) -- precise path (feeds state)
__device__ __forceinline__ float erfinv_xla(float x) {
    float w = -log1pf(-x * x);
    float p;
    if (w < 5.0f) {
        w = w - 2.5f;
        p = 2.81022636e-08f;
        p = fmaf(p, w, 3.43273939e-07f);
        p = fmaf(p, w, -3.5233877e-06f);
        p = fmaf(p, w, -4.39150654e-06f);
        p = fmaf(p, w, 0.00021858087f);
        p = fmaf(p, w, -0.00125372503f);
        p = fmaf(p, w, -0.00417768164f);
        p = fmaf(p, w, 0.246640727f);
        p = fmaf(p, w, 1.50140941f);
    } else {
        w = sqrtf(w) - 3.0f;
        p = -0.000200214257f;
        p = fmaf(p, w, 0.000100950558f);
        p = fmaf(p, w, 0.00134934322f);
        p = fmaf(p, w, -0.00367342844f);
        p = fmaf(p, w, 0.00573950773f);
        p = fmaf(p, w, -0.0076224613f);
        p = fmaf(p, w, 0.00943887047f);
        p = fmaf(p, w, 1.00167406f);
        p = fmaf(p, w, 2.83297682f);
    }
    return p * x;
}

// Exact reference gumbel (libdevice logf), used only on fallback rows.
__device__ __forceinline__ float gumbel_exact(uint32_t bits) {
    float u = bits_to_u01(bits);
    float v = fmaxf(u, TINYF);
    return -logf(-logf(v));
}

// ---------------------------------------------------------------------------
// Fill the 4 constant columns of pf_out once
// ---------------------------------------------------------------------------
__global__ void fill_const_kernel(const float* __restrict__ params,
                                  float* __restrict__ pf) {
    const float p0 = params[0], p1 = params[1], p2 = params[2], p3 = params[3];
    const size_t n = (size_t)TT * KK * BB;
    size_t idx = (size_t)blockIdx.x * blockDim.x + threadIdx.x;
    if (idx < n) {
        float* o = pf + idx * 5;
        o[0] = p0; o[1] = p1; o[2] = p2; o[3] = p3;
    }
}

// ---------------------------------------------------------------------------
// Persistent kernel: 1 CTA per batch element b (r5 layout -- verified best):
//   warps 0-1 : phase A (eps/vol/weights) + phase C (resample/output)
//   warps 2-17: phase B (64x64 categorical), 4 rows each.
// Categorical: argmin of t = e * (1/q) via a single REDUX.MIN.U32 on keys
// (float bits truncated to 26 bits) | particle index, with exact-formula
// fallback for rows whose top-2 gap is within 1e-4 relative.
// ---------------------------------------------------------------------------
__global__ void __launch_bounds__(NTHREADS, 1)
garch_pf_kernel(const float* __restrict__ obs,     // (B, T, 2)
                const float* __restrict__ vol0,    // (K*B, 1)
                const float* __restrict__ params,  // (4,)
                float* __restrict__ out) {
    const int b    = blockIdx.x;
    const int tid  = threadIdx.x;
    const int lane = tid & 31;
    const int warp = tid >> 5;

    const uint32_t one = g_one;    // opaque 1 (forces IMAD adds)

    __shared__ uint2 skey[TT];     // per-step key_t
    __shared__ uint2 sckey[TT];    // fold_in(key_t, 1)
    __shared__ float r_s[TT];      // obs[b, t, 0]
    __shared__ float rinv_s[KK];   // 1/q
    __shared__ float q_s[KK];      // q (fallback + phase C)
    __shared__ float nv_s[KK], wn_s[KK];
    __shared__ float vol_s[KK], w_s[KK];
    __shared__ int   idx_s[KK];
    __shared__ float redm_s[2], reds_s[2];

    for (int t = tid; t < TT; t += NTHREADS) {
        uint2 kt = tf2x32(0u, 42u, 0u, (uint32_t)t, one);
        skey[t]  = kt;
        sckey[t] = tf2x32(kt.x, kt.y, 0u, 1u, one);
        r_s[t]   = obs[((size_t)b * TT + t) * 2];
    }
    if (warp < 2) {
        const int pa = warp * 32 + lane;
        vol_s[pa] = vol0[pa * BB + b];
        w_s[pa]   = 1.0f / 64.0f;
    }
    const float c0 = params[0], q1 = params[1], q2 = params[2], r1 = params[3];
    const float r1e = 0.001f * r1;
    __syncthreads();

    float* __restrict__ y_out = out;                    // (T, B, 1)
    float* __restrict__ pf    = out + (size_t)TT * BB;  // (T, K*B, 5)

    const float MINVAL_N = -0.99999994039535522f;
    const float SQRT2    = 1.41421356237309515f;
    const float LOG2PI   = 1.83787706640934534f;
    const float ALPHA_F  = 0.3f;
    const float UNIFW    = (float)((1.0 - 0.3) / 64.0);
    const float MARGIN   = 1.0001f;   // 1e-4 relative fallback margin

    // B-warp row assignment
    const int w2 = warp - 2;                 // 0..15 for B warps
    float    e0v[4], e1v[4];                 // fast -log(u) per row
    uint32_t b0v[4], b1v[4];                 // raw bits (fallback recompute)

    for (int t = 0; t < TT; t++) {
        if (warp < 2) {
            // ---------------- Phase A: 1 particle/lane across warps 0-1 ----
            const uint2 kt = skey[t];
            const float r    = r_s[t];
            const float rr   = r * r;
            const float q2rr = (q2 * r) * r;
            const int pa = warp * 32 + lane;

            uint2 bl = tf2x32(kt.x, kt.y, 0u, (uint32_t)(pa * BB + b), one);
            float u  = bits_to_u01(bl.x ^ bl.y);
            float v  = fmaxf(MINVAL_N, u * 2.0f + MINVAL_N);
            float eps = SQRT2 * erfinv_xla(v);
            float x   = ((c0 + q1 * vol_s[pa]) + q2rr) + r1e * eps;
            float nvv = fabsf(x) + 1e-8f;
            float ll  = -0.5f * ((rr / nvv + logf(nvv)) + LOG2PI);
            float lw  = logf(w_s[pa] + 1e-12f) + ll;

            // logsumexp over 64 across the two warps
            float m = lw;
#pragma unroll
            for (int o = 16; o; o >>= 1)
                m = fmaxf(m, __shfl_xor_sync(0xffffffffu, m, o));
            if (lane == 0) redm_s[warp] = m;
            asm volatile("bar.sync 1, 64;" ::: "memory");
            float mm = fmaxf(redm_s[0], redm_s[1]);
            float s  = expf(lw - mm);
#pragma unroll
            for (int o = 16; o; o >>= 1)
                s += __shfl_xor_sync(0xffffffffu, s, o);
            if (lane == 0) reds_s[warp] = s;
            asm volatile("bar.sync 1, 64;" ::: "memory");
            float lse = logf(reds_s[0] + reds_s[1]) + mm;

            float wn = expf(lw - lse);
            float q  = ALPHA_F * wn + UNIFW;
            nv_s[pa]   = nvv;
            wn_s[pa]   = wn;
            q_s[pa]    = q;
            rinv_s[pa] = 1.0f / q;
        } else {
            // ---------------- Phase B1: state-independent exp draws --------
            const uint2 ck = sckey[t];
            const uint32_t bb64 = (uint32_t)(b * KK);
#pragma unroll
            for (int ii = 0; ii < 4; ii++) {
                const uint32_t i  = (uint32_t)(w2 * 4 + ii);
                const uint32_t cb = i * 8192u + bb64;   // i*B*K + b*K
                uint2 ga = tf2x32(ck.x, ck.y, 0u, cb + (uint32_t)lane, one);
                uint2 gb = tf2x32(ck.x, ck.y, 0u, cb + (uint32_t)lane + 32u, one);
                b0v[ii] = ga.x ^ ga.y;
                b1v[ii] = gb.x ^ gb.y;
                e0v[ii] = neglog_poly(b0v[ii]);
                e1v[ii] = neglog_poly(b1v[ii]);
            }
        }
        __syncthreads();   // rinv/q published; B1 done

        if (warp >= 2) {
            // -------- Phase B2: REDUX argmin of e/q keys, exact fallback ---
            const float ra = rinv_s[lane];
            const float rb = rinv_s[lane + 32];
#pragma unroll
            for (int ii = 0; ii < 4; ii++) {
                float t0 = e0v[ii] * ra;       // positive -> uint-monotone
                float t1 = e1v[ii] * rb;
                // key = truncated float bits | index (tie -> lowest index)
                uint32_t k0 = (__float_as_uint(t0) & 0xFFFFFFC0u) | (uint32_t)lane;
                uint32_t k1 = (__float_as_uint(t1) & 0xFFFFFFC0u) | (uint32_t)(lane + 32);
                uint32_t km = k0 < k1 ? k0 : k1;
                uint32_t wk = __reduce_min_sync(0xffffffffu, km);
                int bj = (int)(wk & 63u);
                float thr = __uint_as_float(wk & 0xFFFFFFC0u) * MARGIN;
                // near-tie detection (excluding the winner itself)
                bool nr = ((lane      != bj) && (t0 <= thr)) ||
                          ((lane + 32 != bj) && (t1 <= thr));
                if (__ballot_sync(0xffffffffu, nr)) {
                    // exact reference formula: argmax(gumbel + log q)
                    float s0 = gumbel_exact(b0v[ii]) + logf(q_s[lane]);
                    float s1 = gumbel_exact(b1v[ii]) + logf(q_s[lane + 32]);
                    float fb; int fj;
                    if (s1 > s0) { fb = s1; fj = lane + 32; }
                    else         { fb = s0; fj = lane; }
#pragma unroll
                    for (int o = 16; o; o >>= 1) {
                        float ov = __shfl_xor_sync(0xffffffffu, fb, o);
                        int   oj = __shfl_xor_sync(0xffffffffu, fj, o);
                        if (ov > fb || (ov == fb && oj < fj)) { fb = ov; fj = oj; }
                    }
                    bj = fj;
                }
                if (lane == 0) idx_s[w2 * 4 + ii] = bj;
            }
        }
        __syncthreads();   // idx published; B warps free-run into B1(t+1)

        if (warp < 2) {
            // ---------------- Phase C: resample, normalize, outputs --------
            if (warp == 0) {
                const int ia = idx_s[lane], ib = idx_s[lane + 32];
                float vra = nv_s[ia], vrb = nv_s[ib];
                float wra = wn_s[ia] / q_s[ia];
                float wrb = wn_s[ib] / q_s[ib];
                float ssum = wra + wrb;
#pragma unroll
                for (int o = 16; o; o >>= 1)
                    ssum += __shfl_xor_sync(0xffffffffu, ssum, o);
                wra /= ssum; wrb /= ssum;
                vol_s[lane]      = vra; vol_s[lane + 32] = vrb;
                w_s[lane]        = wra; w_s[lane + 32]   = wrb;
                float y = vra * wra + vrb * wrb;
#pragma unroll
                for (int o = 16; o; o >>= 1)
                    y += __shfl_xor_sync(0xffffffffu, y, o);
                if (lane == 0) y_out[(size_t)t * BB + b] = y;
                pf[((size_t)t * (KK * BB) + (size_t)lane * BB + b) * 5 + 4] = vra;
                pf[((size_t)t * (KK * BB) + (size_t)(lane + 32) * BB + b) * 5 + 4] = vrb;
            }
            // warp1 waits for C's state writes before A(t+1)
            asm volatile("bar.sync 1, 64;" ::: "memory");
        }
    }
}

// ---------------------------------------------------------------------------
extern "C" void kernel_launch(void* const* d_in, const int* in_sizes, int n_in,
                              void* d_out, int out_size) {
    const float* obs    = (const float*)d_in[0];  // (128, 2048, 2)
    const float* vol0   = (const float*)d_in[1];  // (8192, 1)
    const float* params = (const float*)d_in[2];  // (4,)
    float* out = (float*)d_out;

    float* pf = out + (size_t)TT * BB;
    fill_const_kernel<<<65536, 256>>>(params, pf);
    garch_pf_kernel<<<BB, NTHREADS>>>(obs, vol0, params, out);
}

// round 10
// speedup vs baseline: 1.2224x; 1.2224x over previous
#include <cuda_runtime.h>
#include <stdint.h>

// Problem constants
#define TT 2048
#define BB 128
#define KK 64
#define NTHREADS 768   // 24 warps: 0-1 = A/C; 2-21 = 3 rows; 22-23 = 2 rows

// ---------------------------------------------------------------------------
// Threefry-2x32, 20 rounds, exactly as jax._src.prng.threefry2x32 (SHF rotate)
// ---------------------------------------------------------------------------
__device__ __forceinline__ uint2 tf2x32(uint32_t k0, uint32_t k1,
                                        uint32_t x0, uint32_t x1) {
    uint32_t ks2 = k0 ^ k1 ^ 0x1BD11BDAu;
    x0 += k0; x1 += k1;
#define TFR(r) { x0 += x1; x1 = __funnelshift_l(x1, x1, (r)); x1 ^= x0; }
    TFR(13) TFR(15) TFR(26) TFR(6)
    x0 += k1; x1 += ks2 + 1u;
    TFR(17) TFR(29) TFR(16) TFR(24)
    x0 += ks2; x1 += k0 + 2u;
    TFR(13) TFR(15) TFR(26) TFR(6)
    x0 += k0; x1 += k1 + 3u;
    TFR(17) TFR(29) TFR(16) TFR(24)
    x0 += k1; x1 += ks2 + 4u;
    TFR(13) TFR(15) TFR(26) TFR(6)
    x0 += ks2; x1 += k0 + 5u;
#undef TFR
    return make_uint2(x0, x1);
}

__device__ __forceinline__ float bits_to_u01(uint32_t bits) {
    return __uint_as_float((bits >> 9) | 0x3f800000u) - 1.0f;
}

#define TINYF 1.17549435082228751e-38f

// Fast polynomial -log(u) for u in (0,1). ~16 instr, NO MUFU.
// Relative error ~2e-7 uniformly (log1p form is exact-dominant near u=1).
__device__ __forceinline__ float neglog_poly(uint32_t bits) {
    float u = fmaxf(bits_to_u01(bits), TINYF);
    int   i = __float_as_int(u);
    int   e = (i >> 23) - 127;
    float m = __int_as_float((i & 0x007fffff) | 0x3f800000);  // [1,2)
    if (m > 1.41421356237f) { m *= 0.5f; e += 1; }            // [0.707,1.414]
    float f = m - 1.0f;
    float z = f * f;
    float p =              7.0376836292e-2f;
    p = fmaf(p, f, -1.1514610310e-1f);
    p = fmaf(p, f,  1.1676998740e-1f);
    p = fmaf(p, f, -1.2420140846e-1f);
    p = fmaf(p, f,  1.4249322787e-1f);
    p = fmaf(p, f, -1.6668057665e-1f);
    p = fmaf(p, f,  2.0000714765e-1f);
    p = fmaf(p, f, -2.4999993993e-1f);
    p = fmaf(p, f,  3.3333331174e-1f);
    float y = (f * z) * p;
    float ef = (float)e;
    y = fmaf(ef, -2.12194440e-4f, y);   // ln2 low part
    y = fmaf(z, -0.5f, y);
    float r = f + y + ef * 0.693359375f;  // ln2 high part
    return -r;
}

// XLA/CHLO ErfInv32 polynomial (Giles) -- precise path (feeds state)
__device__ __forceinline__ float erfinv_xla(float x) {
    float w = -log1pf(-x * x);
    float p;
    if (w < 5.0f) {
        w = w - 2.5f;
        p = 2.81022636e-08f;
        p = fmaf(p, w, 3.43273939e-07f);
        p = fmaf(p, w, -3.5233877e-06f);
        p = fmaf(p, w, -4.39150654e-06f);
        p = fmaf(p, w, 0.00021858087f);
        p = fmaf(p, w, -0.00125372503f);
        p = fmaf(p, w, -0.00417768164f);
        p = fmaf(p, w, 0.246640727f);
        p = fmaf(p, w, 1.50140941f);
    } else {
        w = sqrtf(w) - 3.0f;
        p = -0.000200214257f;
        p = fmaf(p, w, 0.000100950558f);
        p = fmaf(p, w, 0.00134934322f);
        p = fmaf(p, w, -0.00367342844f);
        p = fmaf(p, w, 0.00573950773f);
        p = fmaf(p, w, -0.0076224613f);
        p = fmaf(p, w, 0.00943887047f);
        p = fmaf(p, w, 1.00167406f);
        p = fmaf(p, w, 2.83297682f);
    }
    return p * x;
}

// Exact reference gumbel (libdevice logf), used only on fallback rows.
__device__ __forceinline__ float gumbel_exact(uint32_t bits) {
    float u = bits_to_u01(bits);
    float v = fmaxf(u, TINYF);
    return -logf(-logf(v));
}

// ---------------------------------------------------------------------------
// Fill the 4 constant columns of pf_out once
// ---------------------------------------------------------------------------
__global__ void fill_const_kernel(const float* __restrict__ params,
                                  float* __restrict__ pf) {
    const float p0 = params[0], p1 = params[1], p2 = params[2], p3 = params[3];
    const size_t n = (size_t)TT * KK * BB;
    size_t idx = (size_t)blockIdx.x * blockDim.x + threadIdx.x;
    if (idx < n) {
        float* o = pf + idx * 5;
        o[0] = p0; o[1] = p1; o[2] = p2; o[3] = p3;
    }
}

// ---------------------------------------------------------------------------
// Persistent kernel: 1 CTA per batch element b. r8 structure, wider B:
//   warps 0-1 : phase A only (starts immediately; latency-critical) + C(w0)
//   warps 2-21: 3 categorical rows each (rows 0..59)
//   warps22-23: 2 categorical rows each (rows 60..63)
// Categorical: argmin of t = e * (1/q) via a single REDUX.MIN.U32 on keys
// (float bits truncated to 26 bits) | particle index, with exact-formula
// fallback for rows whose top-2 gap is within 1e-4 relative.
// ---------------------------------------------------------------------------
__global__ void __launch_bounds__(NTHREADS, 1)
garch_pf_kernel(const float* __restrict__ obs,     // (B, T, 2)
                const float* __restrict__ vol0,    // (K*B, 1)
                const float* __restrict__ params,  // (4,)
                float* __restrict__ out) {
    const int b    = blockIdx.x;
    const int tid  = threadIdx.x;
    const int lane = tid & 31;
    const int warp = tid >> 5;

    __shared__ uint2 skey[TT];     // per-step key_t
    __shared__ uint2 sckey[TT];    // fold_in(key_t, 1)
    __shared__ float r_s[TT];      // obs[b, t, 0]
    __shared__ float rinv_s[KK];   // 1/q
    __shared__ float q_s[KK];      // q (fallback + phase C)
    __shared__ float nv_s[KK], wn_s[KK];
    __shared__ float vol_s[KK], w_s[KK];
    __shared__ int   idx_s[KK];
    __shared__ float redm_s[2], reds_s[2];

    for (int t = tid; t < TT; t += NTHREADS) {
        uint2 kt = tf2x32(0u, 42u, 0u, (uint32_t)t);
        skey[t]  = kt;
        sckey[t] = tf2x32(kt.x, kt.y, 0u, 1u);
        r_s[t]   = obs[((size_t)b * TT + t) * 2];
    }
    if (warp < 2) {
        const int pa = warp * 32 + lane;
        vol_s[pa] = vol0[pa * BB + b];
        w_s[pa]   = 1.0f / 64.0f;
    }
    const float c0 = params[0], q1 = params[1], q2 = params[2], r1 = params[3];
    const float r1e = 0.001f * r1;
    __syncthreads();

    float* __restrict__ y_out = out;                    // (T, B, 1)
    float* __restrict__ pf    = out + (size_t)TT * BB;  // (T, K*B, 5)

    const float MINVAL_N = -0.99999994039535522f;
    const float SQRT2    = 1.41421356237309515f;
    const float LOG2PI   = 1.83787706640934534f;
    const float ALPHA_F  = 0.3f;
    const float UNIFW    = (float)((1.0 - 0.3) / 64.0);
    const float MARGIN   = 1.0001f;   // 1e-4 relative fallback margin

    // B-warp row assignment: w2 = warp-2 in 0..21.
    // w2 < 20  -> 3 rows at row0 = w2*3        (rows 0..59)
    // w2 >= 20 -> 2 rows at row0 = 60+(w2-20)*2 (rows 60..63)
    const int w2    = warp - 2;
    const int nrows = (w2 < 20) ? 3 : 2;
    const int row0  = (w2 < 20) ? w2 * 3 : 60 + (w2 - 20) * 2;

    float    e0v[3], e1v[3];                 // fast -log(u) per row
    uint32_t b0v[3], b1v[3];                 // raw bits (fallback recompute)

    for (int t = 0; t < TT; t++) {
        if (warp < 2) {
            // ---------------- Phase A: 1 particle/lane across warps 0-1 ----
            const uint2 kt = skey[t];
            const float r    = r_s[t];
            const float rr   = r * r;
            const float q2rr = (q2 * r) * r;
            const int pa = warp * 32 + lane;

            uint2 bl = tf2x32(kt.x, kt.y, 0u, (uint32_t)(pa * BB + b));
            float u  = bits_to_u01(bl.x ^ bl.y);
            float v  = fmaxf(MINVAL_N, u * 2.0f + MINVAL_N);
            float eps = SQRT2 * erfinv_xla(v);
            float x   = ((c0 + q1 * vol_s[pa]) + q2rr) + r1e * eps;
            float nvv = fabsf(x) + 1e-8f;
            float ll  = -0.5f * ((rr / nvv + logf(nvv)) + LOG2PI);
            float lw  = logf(w_s[pa] + 1e-12f) + ll;

            // logsumexp over 64 across the two warps
            float m = lw;
#pragma unroll
            for (int o = 16; o; o >>= 1)
                m = fmaxf(m, __shfl_xor_sync(0xffffffffu, m, o));
            if (lane == 0) redm_s[warp] = m;
            asm volatile("bar.sync 1, 64;" ::: "memory");
            float mm = fmaxf(redm_s[0], redm_s[1]);
            float s  = expf(lw - mm);
#pragma unroll
            for (int o = 16; o; o >>= 1)
                s += __shfl_xor_sync(0xffffffffu, s, o);
            if (lane == 0) reds_s[warp] = s;
            asm volatile("bar.sync 1, 64;" ::: "memory");
            float lse = logf(reds_s[0] + reds_s[1]) + mm;

            float wn = expf(lw - lse);
            float q  = ALPHA_F * wn + UNIFW;
            nv_s[pa]   = nvv;
            wn_s[pa]   = wn;
            q_s[pa]    = q;
            rinv_s[pa] = 1.0f / q;
        } else {
            // ---------------- Phase B1: state-independent exp draws --------
            const uint2 ck = sckey[t];
            const uint32_t bb64 = (uint32_t)(b * KK);
#pragma unroll
            for (int ii = 0; ii < 3; ii++) {
                if (ii < nrows) {
                    const uint32_t i  = (uint32_t)(row0 + ii);
                    const uint32_t cb = i * 8192u + bb64;   // i*B*K + b*K
                    uint2 ga = tf2x32(ck.x, ck.y, 0u, cb + (uint32_t)lane);
                    uint2 gb = tf2x32(ck.x, ck.y, 0u, cb + (uint32_t)lane + 32u);
                    b0v[ii] = ga.x ^ ga.y;
                    b1v[ii] = gb.x ^ gb.y;
                    e0v[ii] = neglog_poly(b0v[ii]);
                    e1v[ii] = neglog_poly(b1v[ii]);
                }
            }
        }
        __syncthreads();   // rinv/q published; B1 done

        if (warp >= 2) {
            // -------- Phase B2: REDUX argmin of e/q keys, exact fallback ---
            const float ra = rinv_s[lane];
            const float rb = rinv_s[lane + 32];
#pragma unroll
            for (int ii = 0; ii < 3; ii++) {
                if (ii < nrows) {
                    float t0 = e0v[ii] * ra;       // positive -> uint-monotone
                    float t1 = e1v[ii] * rb;
                    // key = truncated float bits | index (tie -> lowest index)
                    uint32_t k0 = (__float_as_uint(t0) & 0xFFFFFFC0u) | (uint32_t)lane;
                    uint32_t k1 = (__float_as_uint(t1) & 0xFFFFFFC0u) | (uint32_t)(lane + 32);
                    uint32_t km = k0 < k1 ? k0 : k1;
                    uint32_t wk = __reduce_min_sync(0xffffffffu, km);
                    int bj = (int)(wk & 63u);
                    float thr = __uint_as_float(wk & 0xFFFFFFC0u) * MARGIN;
                    // near-tie detection (excluding the winner itself)
                    bool nr = ((lane      != bj) && (t0 <= thr)) ||
                              ((lane + 32 != bj) && (t1 <= thr));
                    if (__ballot_sync(0xffffffffu, nr)) {
                        // exact reference formula: argmax(gumbel + log q)
                        float s0 = gumbel_exact(b0v[ii]) + logf(q_s[lane]);
                        float s1 = gumbel_exact(b1v[ii]) + logf(q_s[lane + 32]);
                        float fb; int fj;
                        if (s1 > s0) { fb = s1; fj = lane + 32; }
                        else         { fb = s0; fj = lane; }
#pragma unroll
                        for (int o = 16; o; o >>= 1) {
                            float ov = __shfl_xor_sync(0xffffffffu, fb, o);
                            int   oj = __shfl_xor_sync(0xffffffffu, fj, o);
                            if (ov > fb || (ov == fb && oj < fj)) { fb = ov; fj = oj; }
                        }
                        bj = fj;
                    }
                    if (lane == 0) idx_s[row0 + ii] = bj;
                }
            }
        }
        __syncthreads();   // idx published; B warps free-run into B1(t+1)

        if (warp < 2) {
            // ---------------- Phase C: resample, normalize, outputs --------
            if (warp == 0) {
                const int ia = idx_s[lane], ib = idx_s[lane + 32];
                float vra = nv_s[ia], vrb = nv_s[ib];
                float wra = wn_s[ia] / q_s[ia];
                float wrb = wn_s[ib] / q_s[ib];
                float ssum = wra + wrb;
#pragma unroll
                for (int o = 16; o; o >>= 1)
                    ssum += __shfl_xor_sync(0xffffffffu, ssum, o);
                wra /= ssum; wrb /= ssum;
                vol_s[lane]      = vra; vol_s[lane + 32] = vrb;
                w_s[lane]        = wra; w_s[lane + 32]   = wrb;
                float y = vra * wra + vrb * wrb;
#pragma unroll
                for (int o = 16; o; o >>= 1)
                    y += __shfl_xor_sync(0xffffffffu, y, o);
                if (lane == 0) y_out[(size_t)t * BB + b] = y;
                pf[((size_t)t * (KK * BB) + (size_t)lane * BB + b) * 5 + 4] = vra;
                pf[((size_t)t * (KK * BB) + (size_t)(lane + 32) * BB + b) * 5 + 4] = vrb;
            }
            // warp1 waits for C's state writes before A(t+1)
            asm volatile("bar.sync 1, 64;" ::: "memory");
        }
    }
}

// ---------------------------------------------------------------------------
extern "C" void kernel_launch(void* const* d_in, const int* in_sizes, int n_in,
                              void* d_out, int out_size) {
    const float* obs    = (const float*)d_in[0];  // (128, 2048, 2)
    const float* vol0   = (const float*)d_in[1];  // (8192, 1)
    const float* params = (const float*)d_in[2];  // (4,)
    float* out = (float*)d_out;

    float* pf = out + (size_t)TT * BB;
    fill_const_kernel<<<65536, 256>>>(params, pf);
    garch_pf_kernel<<<BB, NTHREADS>>>(obs, vol0, params, out);
}